// round 13
// baseline (speedup 1.0000x reference)
#include <cuda_runtime.h>
#include <math.h>

#define CCH   64
#define PIX   262144
#define NCLS  11
#define GRIDP 128
#define GRID  148
#define NTHR  512
#define NG    (PIX / 32)      // 8192 pixel groups of 32
#define ITER4 14              // 14*4 = 56 = ceil(NG/GRID)

// ---------------- device-global scratch (no allocation) ----------------
__device__ __align__(8) unsigned short g_pm[PIX];    // packed 16-bit instance masks
__device__ float g_invn[PIX];                        // 1/||X2_p||
__device__ int   g_pcntT[16][GRIDP];                 // counts, transposed
__device__ float g_p1T[1024][GRID];                  // transposed per-channel sums (X1)
__device__ float g_qT[16][2 * GRID];                 // sumsq partials (both y-halves)
__device__ float g_p2T[1024][GRID];                  // transposed Z partials
__device__ float g_red1[1040];                       // [0:1024) pcs, [1024:1040) sumsq
__device__ float g_red2[1024];
__device__ float g_redc[16];

// ---------------- f32x2 helpers ----------------
__device__ __forceinline__ unsigned long long pack2(float lo, float hi) {
    unsigned long long r;
    asm("mov.b64 %0, {%1, %2};" : "=l"(r) : "f"(lo), "f"(hi));
    return r;
}
__device__ __forceinline__ float2 unpack2(unsigned long long v) {
    float2 f;
    asm("mov.b64 {%0, %1}, %2;" : "=f"(f.x), "=f"(f.y) : "l"(v));
    return f;
}
__device__ __forceinline__ unsigned long long addf2(unsigned long long a, unsigned long long b) {
    unsigned long long r;
    asm("add.rn.f32x2 %0, %1, %2;" : "=l"(r) : "l"(a), "l"(b));
    return r;
}
__device__ __forceinline__ unsigned long long mulf2(unsigned long long a, unsigned long long b) {
    unsigned long long r;
    asm("mul.rn.f32x2 %0, %1, %2;" : "=l"(r) : "l"(a), "l"(b));
    return r;
}
// if (b) { a01 += x01 (packed); q += s2; }
__device__ __forceinline__ void macc_p2q(unsigned long long &a01, float &q,
                                         unsigned long long x01, float s2, unsigned b) {
    asm("{ .reg .pred p;\n\t"
        "setp.ne.u32 p, %4, 0;\n\t"
        "@p add.rn.f32x2 %0, %0, %2;\n\t"
        "@p add.f32 %1, %1, %3; }"
        : "+l"(a01), "+f"(q)
        : "l"(x01), "f"(s2), "r"(b));
}
// if (b) { a01 += x01 (packed); }
__device__ __forceinline__ void macc_p2(unsigned long long &a01,
                                        unsigned long long x01, unsigned b) {
    asm("{ .reg .pred p;\n\t"
        "setp.ne.u32 p, %2, 0;\n\t"
        "@p add.rn.f32x2 %0, %0, %1; }"
        : "+l"(a01)
        : "l"(x01), "r"(b));
}

// ---------------- kprep: pack masks + counts + X2 inverse norms ----------------
__global__ __launch_bounds__(NTHR, 1) void kprep(const int* __restrict__ masks,
                                                 const float* __restrict__ X2) {
    __shared__ int s_cnt[16][16];
    int tid = threadIdx.x, lane = tid & 31, w = tid >> 5;
    int q4 = blockIdx.x * NTHR + tid;   // quad index; GRIDP*NTHR == PIX/4 exactly

    // X2 inverse norms for this quad (deep unroll for MLP)
    {
        const float4* X2v = (const float4*)X2;
        float4 n2 = make_float4(0.f, 0.f, 0.f, 0.f);
#pragma unroll 16
        for (int c = 0; c < CCH; c++) {
            float4 x = X2v[(size_t)c * (PIX / 4) + q4];
            n2.x = fmaf(x.x, x.x, n2.x);
            n2.y = fmaf(x.y, x.y, n2.y);
            n2.z = fmaf(x.z, x.z, n2.z);
            n2.w = fmaf(x.w, x.w, n2.w);
        }
        float4 inv;
        inv.x = rsqrtf(n2.x); inv.y = rsqrtf(n2.y);
        inv.z = rsqrtf(n2.z); inv.w = rsqrtf(n2.w);
        ((float4*)g_invn)[q4] = inv;
    }

    const int4* m4 = (const int4*)masks;
    unsigned pm0 = 0, pm1 = 0, pm2 = 0, pm3 = 0;
    int cnt[16];
#pragma unroll
    for (int k = 0; k < 16; k++) {
        int4 v = m4[(size_t)k * (PIX / 4) + q4];
        pm0 |= (unsigned)v.x << k;
        pm1 |= (unsigned)v.y << k;
        pm2 |= (unsigned)v.z << k;
        pm3 |= (unsigned)v.w << k;
        cnt[k] = (v.x + v.y) + (v.z + v.w);
    }
    {
        ushort4 st;
        st.x = (unsigned short)pm0; st.y = (unsigned short)pm1;
        st.z = (unsigned short)pm2; st.w = (unsigned short)pm3;
        ((ushort4*)g_pm)[q4] = st;
    }
#pragma unroll
    for (int k = 0; k < 16; k++) {
#pragma unroll
        for (int s = 16; s > 0; s >>= 1)
            cnt[k] += __shfl_xor_sync(0xffffffffu, cnt[k], s);
    }
    if (lane < 16) s_cnt[w][lane] = cnt[lane];
    __syncthreads();
    if (tid < 16) {
        int s = 0;
#pragma unroll
        for (int w2 = 0; w2 < 16; w2++) s += s_cnt[w2][tid];
        g_pcntT[tid][blockIdx.x] = s;
    }
}

// ---------------- k1: masked 2-channel sums of X1 + sumsq (depth-4, no spills) ----
// grid (148, 2): x = pixel stripe, y = channel half. warp owns 2 channels.
__global__ __launch_bounds__(NTHR, 1) void k1(const float* __restrict__ X1) {
    __shared__ float s_q[16][17];
    int tid = threadIdx.x, lane = tid & 31, w = tid >> 5;
    int cb = blockIdx.y * 32 + w * 2;

    unsigned long long a01[16];
    float q[16];
#pragma unroll
    for (int k = 0; k < 16; k++) { a01[k] = 0ull; q[k] = 0.f; }

    const float* b0 = X1 + (size_t)(cb + 0) * PIX;
    const float* b1 = X1 + (size_t)(cb + 1) * PIX;

#define LD1(G, PM, X0, X1r)                                        \
    {                                                              \
        int gc = min((G), NG - 1);                                 \
        int p = gc * 32 + lane;                                    \
        PM = ((G) < NG) ? (unsigned)g_pm[p] : 0u;                  \
        X0 = b0[p]; X1r = b1[p];                                   \
    }
#define PROC1(PM, X0, X1r)                                                  \
    {                                                                       \
        unsigned long long X01 = pack2(X0, X1r);                            \
        float s2 = fmaf(X0, X0, X1r * X1r);                                 \
        _Pragma("unroll")                                                   \
        for (int k = 0; k < 16; k++)                                        \
            macc_p2q(a01[k], q[k], X01, s2, PM & (1u << k));                \
    }
#define PHASE1(ST, OFF)                                                     \
    {                                                                       \
        unsigned pmc = pm##ST;                                              \
        float c0 = ST##0, c1 = ST##1;                                       \
        LD1(g + (OFF) * GRID, pm##ST, ST##0, ST##1);                        \
        PROC1(pmc, c0, c1);                                                 \
    }

    unsigned pmA, pmB, pmC, pmD;
    float A0, A1, B0, B1, C0, C1, D0, D1;
    int g = blockIdx.x;

    LD1(g + 0 * GRID, pmA, A0, A1);
    LD1(g + 1 * GRID, pmB, B0, B1);
    LD1(g + 2 * GRID, pmC, C0, C1);
    LD1(g + 3 * GRID, pmD, D0, D1);
#pragma unroll 1
    for (int it = 0; it < ITER4; it++) {
        PHASE1(A, 4)
        PHASE1(B, 5)
        PHASE1(C, 6)
        PHASE1(D, 7)
        g += 4 * GRID;
    }

#pragma unroll
    for (int k = 0; k < 16; k++) {
#pragma unroll
        for (int s = 16; s > 0; s >>= 1) {
            a01[k] = addf2(a01[k], __shfl_xor_sync(0xffffffffu, a01[k], s));
            q[k] += __shfl_xor_sync(0xffffffffu, q[k], s);
        }
    }
    if (lane == 0) {
#pragma unroll
        for (int k = 0; k < 16; k++) {
            float2 u = unpack2(a01[k]);
            g_p1T[k * 64 + cb + 0][blockIdx.x] = u.x;
            g_p1T[k * 64 + cb + 1][blockIdx.x] = u.y;
            s_q[w][k] = q[k];
        }
    }
    __syncthreads();
    if (tid < 16) {
        float s = 0.f;
#pragma unroll
        for (int w2 = 0; w2 < 16; w2++) s += s_q[w2][tid];
        g_qT[tid][blockIdx.y * GRID + blockIdx.x] = s;
    }
}

// ---------------- k4: masked 2-channel sums of normalized X2 (depth-4) ----------
__global__ __launch_bounds__(NTHR, 1) void k4(const float* __restrict__ X2) {
    int tid = threadIdx.x, lane = tid & 31, w = tid >> 5;
    int cb = blockIdx.y * 32 + w * 2;

    unsigned long long a01[16];
#pragma unroll
    for (int k = 0; k < 16; k++) a01[k] = 0ull;

    const float* b0 = X2 + (size_t)(cb + 0) * PIX;
    const float* b1 = X2 + (size_t)(cb + 1) * PIX;

#define LD2(G, PM, IV, X0, X1r)                                    \
    {                                                              \
        int gc = min((G), NG - 1);                                 \
        int p = gc * 32 + lane;                                    \
        PM = ((G) < NG) ? (unsigned)g_pm[p] : 0u;                  \
        IV = g_invn[p];                                            \
        X0 = b0[p]; X1r = b1[p];                                   \
    }
#define PROC2(PM, IV, X0, X1r)                                              \
    {                                                                       \
        unsigned long long Y01 = mulf2(pack2(X0, X1r), pack2(IV, IV));      \
        _Pragma("unroll")                                                   \
        for (int k = 0; k < 16; k++)                                        \
            macc_p2(a01[k], Y01, PM & (1u << k));                           \
    }
#define PHASE2(ST, OFF)                                                     \
    {                                                                       \
        unsigned pmc = pm##ST; float ivc = iv##ST;                          \
        float c0 = ST##0, c1 = ST##1;                                       \
        LD2(g + (OFF) * GRID, pm##ST, iv##ST, ST##0, ST##1);                \
        PROC2(pmc, ivc, c0, c1);                                            \
    }

    unsigned pmA, pmB, pmC, pmD;
    float ivA, ivB, ivC, ivD;
    float A0, A1, B0, B1, C0, C1, D0, D1;
    int g = blockIdx.x;

    LD2(g + 0 * GRID, pmA, ivA, A0, A1);
    LD2(g + 1 * GRID, pmB, ivB, B0, B1);
    LD2(g + 2 * GRID, pmC, ivC, C0, C1);
    LD2(g + 3 * GRID, pmD, ivD, D0, D1);
#pragma unroll 1
    for (int it = 0; it < ITER4; it++) {
        PHASE2(A, 4)
        PHASE2(B, 5)
        PHASE2(C, 6)
        PHASE2(D, 7)
        g += 4 * GRID;
    }

#pragma unroll
    for (int k = 0; k < 16; k++) {
#pragma unroll
        for (int s = 16; s > 0; s >>= 1)
            a01[k] = addf2(a01[k], __shfl_xor_sync(0xffffffffu, a01[k], s));
    }
    if (lane == 0) {
#pragma unroll
        for (int k = 0; k < 16; k++) {
            float2 u = unpack2(a01[k]);
            g_p2T[k * 64 + cb + 0][blockIdx.x] = u.x;
            g_p2T[k * 64 + cb + 1][blockIdx.x] = u.y;
        }
    }
}

// ---------------- kred: warp-per-value coalesced reduce ----------------
__global__ __launch_bounds__(NTHR, 1) void kred() {
    int lane = threadIdx.x & 31;
    int v = blockIdx.x * 16 + (threadIdx.x >> 5);   // <<<130,512>>> -> 2080 warps
    if (v < 1024) {
        const float* row = g_p1T[v];
        float s = 0.f;
#pragma unroll
        for (int i = 0; i < 5; i++) {
            int idx = lane + i * 32;
            s += (idx < GRID) ? row[idx] : 0.f;
        }
#pragma unroll
        for (int sh = 16; sh > 0; sh >>= 1) s += __shfl_xor_sync(0xffffffffu, s, sh);
        if (lane == 0) g_red1[v] = s;
    } else if (v < 1040) {
        const float* row = g_qT[v - 1024];
        float s = 0.f;
#pragma unroll
        for (int i = 0; i < 10; i++) {
            int idx = lane + i * 32;
            s += (idx < 2 * GRID) ? row[idx] : 0.f;
        }
#pragma unroll
        for (int sh = 16; sh > 0; sh >>= 1) s += __shfl_xor_sync(0xffffffffu, s, sh);
        if (lane == 0) g_red1[v] = s;
    } else if (v < 2064) {
        const float* row = g_p2T[v - 1040];
        float s = 0.f;
#pragma unroll
        for (int i = 0; i < 5; i++) {
            int idx = lane + i * 32;
            s += (idx < GRID) ? row[idx] : 0.f;
        }
#pragma unroll
        for (int sh = 16; sh > 0; sh >>= 1) s += __shfl_xor_sync(0xffffffffu, s, sh);
        if (lane == 0) g_red2[v - 1040] = s;
    } else if (v < 2080) {
        const int* row = g_pcntT[v - 2064];
        int s = 0;
#pragma unroll
        for (int i = 0; i < 4; i++) s += row[lane + i * 32];
#pragma unroll
        for (int sh = 16; sh > 0; sh >>= 1) s += __shfl_xor_sync(0xffffffffu, s, sh);
        if (lane == 0) g_redc[v - 2064] = (float)s;
    }
}

// ---------------- kfinal: stats + sim + class/bucket outputs ----------------
__device__ __forceinline__ bool gpred(int b, int l) {
    if (b == 0) return (l >= 1) && (l <= 8);
    if (b == 1) return (l >= 3) && (l <= 10);
    return ((l >= 1) && (l <= 2)) || ((l >= 9) && (l <= 10));
}

__global__ void kfinal(const int* __restrict__ labels, float* __restrict__ out) {
    __shared__ float s_mean[1024];
    __shared__ float s_Z[1024];
    __shared__ float s_cnt[16], s_nm[16], s_std[16];
    __shared__ float s_sim[256];
    __shared__ int s_lab[16];
    int tid = threadIdx.x;

    for (int v = tid; v < 1024; v += NTHR) {
        s_mean[v] = g_red1[v];
        s_Z[v] = g_red2[v];
    }
    if (tid >= 64 && tid < 80) s_lab[tid - 64] = labels[tid - 64];
    __syncthreads();

    if (tid < 16) {
        int k = tid;
        float counts = g_redc[k];
        float cnt = fmaxf(counts, 1.f);
        float inv = 1.f / cnt;
        float sa = 0.f, nm2 = 0.f;
        for (int c = 0; c < 64; c++) {
            float pcs = s_mean[k * 64 + c];
            sa += pcs;
            float m = pcs * inv;
            s_mean[k * 64 + c] = m;
            nm2 = fmaf(m, m, nm2);
        }
        s_nm[k] = sqrtf(nm2);
        s_cnt[k] = cnt;
        float ne = counts * 64.f;
        float ma = sa / fmaxf(ne, 1.f);
        float var = (g_red1[1024 + k] - ne * ma * ma) / fmaxf(ne - 1.f, 1.f);
        s_std[k] = sqrtf(fmaxf(var, 0.f));
    }
    __syncthreads();

    if (tid < 256) {
        int i = tid >> 4, j = tid & 15;
        float d = 0.f;
        for (int c = 0; c < 64; c++)
            d = fmaf(s_mean[i * 64 + c], s_Z[j * 64 + c], d);
        s_sim[tid] = d / (fmaxf(s_nm[i], 1e-20f) * s_cnt[j]);
    }
    __syncthreads();

    if (tid < NCLS) {
        int cl = tid;
        float cc = 0.f, inst = 0.f, cstd = 0.f, csim = 0.f;
        for (int k = 0; k < 16; k++) {
            if (s_lab[k] == cl) {
                cc += 1.f;
                inst += s_sim[k * 16 + k];
                cstd += s_std[k];
            }
        }
        for (int i = 0; i < 16; i++) {
            if (s_lab[i] != cl) continue;
            for (int j = 0; j < 16; j++)
                if (j != i && s_lab[j] == cl) csim += s_sim[i * 16 + j];
        }
        bool many = cc > 1.f;
        out[cl]      = many ? inst / fmaxf(cc, 1.f) : inst;
        out[11 + cl] = many ? csim / fmaxf(cc * (cc - 1.f), 1.f) : csim;
        out[25 + cl] = many ? cstd / fmaxf(cc, 1.f) : cstd;
    }
    if (tid >= 32 && tid < 35) {
        int b = tid - 32;
        float s = 0.f;
        int c = 0;
        for (int i = 0; i < 16; i++) {
            if (!gpred(b, s_lab[i])) continue;
            for (int j = 0; j < 16; j++) {
                if (s_lab[j] != s_lab[i] && gpred(b, s_lab[j])) {
                    c++;
                    s += s_sim[i * 16 + j];
                }
            }
        }
        out[22 + b] = (c > 1) ? s / (float)c : s;
    }
}

// ---------------- launcher ----------------
extern "C" void kernel_launch(void* const* d_in, const int* in_sizes, int n_in,
                              void* d_out, int out_size) {
    const float* v1     = (const float*)d_in[0];
    const float* v2     = (const float*)d_in[1];
    const int*   masks  = (const int*)d_in[2];
    const int*   labels = (const int*)d_in[3];
    float* out = (float*)d_out;

    dim3 grid2(GRID, 2);
    kprep<<<GRIDP, NTHR>>>(masks, v2);
    k1<<<grid2, NTHR>>>(v1);
    k4<<<grid2, NTHR>>>(v2);
    kred<<<130, NTHR>>>();
    kfinal<<<1, NTHR>>>(labels, out);
}